// round 8
// baseline (speedup 1.0000x reference)
#include <cuda_runtime.h>
#include <cstdint>

// Problem constants (fixed by the reference).
#define C_OUT   96
#define NK      11
#define C_IN    1056
#define GB      8
#define NTILES  (C_OUT*GB)         // 768 tiles, one per (b, c_out)
#define HOUT    56
#define WOUT    56
#define HIN     60
#define EP      2
#define PLANE   3600
#define PLANE_BYTES 14400
#define NPIX    3136
#define NCW     28                 // compute warps
#define THREADS (NCW*32 + 32)      // 928: 28 compute warps + 1 producer warp
#define OUT_PLANE ((size_t)GB*C_OUT*NPIX)
#define KROWS   32                 // h = h0 + 32*k, k in {0,1}
#define KSTEP   (KROWS*HIN)        // 1920 floats

// Plane ring with shared inter-slot zero guards.
// v-row index in [-27, 86] -> offsets [-1618, +5217] from plane start;
// 1620-float guards (shared between adjacent slots) absorb all OOB reads.
#define NSLOT       10
#define GUARD       1620
#define SLOT_STRIDE (PLANE + GUARD)                 // 5220
#define SM_DATA     (NSLOT*SLOT_STRIDE + GUARD)     // 53820 floats
#define OFF_TAB     SM_DATA                          // 2 x 44 float4 (double buffer)
#define OFF_WID     (OFF_TAB + 352)                  // 2 x 12 floats
#define OFF_Q       (OFF_WID + 24)                   // 4 ints (tile queue)
#define OFF_BAR     (OFF_Q + 4)                      // 10 full + 10 empty u64
#define SMEM_FLOATS (OFF_BAR + 40)
#define SMEM_BYTES  (SMEM_FLOATS * 4)                // ~217 KB

__device__ int g_tile_ctr;
__global__ void reset_kernel() { g_tile_ctr = 0; }

__device__ __forceinline__ uint32_t smem_u32(const void* p) {
    uint32_t a;
    asm("{ .reg .u64 t; cvta.to.shared.u64 t, %1; cvt.u32.u64 %0, t; }"
        : "=r"(a) : "l"(p));
    return a;
}
__device__ __forceinline__ void mbar_init(uint32_t mbar, uint32_t cnt) {
    asm volatile("mbarrier.init.shared.b64 [%0], %1;" :: "r"(mbar), "r"(cnt) : "memory");
}
__device__ __forceinline__ void mbar_wait(uint32_t mbar, int parity) {
    asm volatile(
        "{\n\t.reg .pred P;\n"
        "W_%=:\n\t"
        "mbarrier.try_wait.parity.acquire.cta.shared::cta.b64 P, [%0], %1, 0x989680;\n\t"
        "@P bra D_%=;\n\t"
        "bra W_%=;\n"
        "D_%=:\n\t}"
        :: "r"(mbar), "r"(parity) : "memory");
}

// Packed f32x2 helpers (Blackwell: FFMA2 only reachable via PTX fma.rn.f32x2).
__device__ __forceinline__ unsigned long long pk2(float a, float b) {
    unsigned long long r;
    asm("mov.b64 %0, {%1, %2};" : "=l"(r) : "f"(a), "f"(b));
    return r;
}
__device__ __forceinline__ void ffma2(unsigned long long& d,
                                      unsigned long long a, unsigned long long b) {
    asm("fma.rn.f32x2 %0, %1, %2, %0;" : "+l"(d) : "l"(a), "l"(b));
}
__device__ __forceinline__ float2 unpk2(unsigned long long v) {
    float2 r;
    asm("mov.b64 {%0, %1}, %2;" : "=f"(r.x), "=f"(r.y) : "l"(v));
    return r;
}
__device__ __forceinline__ unsigned long long lds64(const float* p) {
    return *reinterpret_cast<const unsigned long long*>(p);   // 8B-aligned by construction
}

__global__ __launch_bounds__(THREADS, 1)
void addshift_kernel(const float* __restrict__ x,
                     const float* __restrict__ w1,
                     const float* __restrict__ w2,
                     const float* __restrict__ w3,
                     const int*   __restrict__ pad_hv,
                     const int*   __restrict__ idx_identit,
                     float* __restrict__ out)
{
    extern __shared__ float smem[];
    float4* tab = (float4*)(smem + OFF_TAB);   // [2][44]
    float*  wid = smem + OFF_WID;              // [2][12]
    int*    q   = (int*)(smem + OFF_Q);

    const int tid = threadIdx.x;
    const uint32_t smem_base = smem_u32(smem);
    const uint32_t fbar0 = smem_base + (uint32_t)OFF_BAR * 4u;        // full[s]
    const uint32_t ebar0 = fbar0 + 8u * NSLOT;                        // empty[s]

    // Zero data region once (guards stay zero; plane bytes overwritten by TMA).
    {
        float4* d = (float4*)smem;
        const float4 z = make_float4(0.f, 0.f, 0.f, 0.f);
        for (int i = tid; i < SM_DATA / 4; i += THREADS) d[i] = z;
    }
    if (tid == 0) {
        for (int s = 0; s < NSLOT; s++) {
            mbar_init(fbar0 + 8u * s, 1);
            mbar_init(ebar0 + 8u * s, NCW);
        }
    }
    __syncthreads();   // the only full-CTA barrier

    // ================= producer warp =================
    if (tid >= NCW * 32) {
        if (tid == NCW * 32) {
            asm volatile("fence.proxy.async.shared::cta;" ::: "memory");
            int pnk = 0, ptq = 0;
            for (int p = 0;; p++) {
                int s = p % NSLOT;
                if (p >= NSLOT)
                    mbar_wait(ebar0 + 8u * s, ((p - NSLOT) / NSLOT) & 1);
                if (pnk == 0) {
                    int t = atomicAdd(&g_tile_ctr, 1);
                    q[ptq & 3] = (t < NTILES) ? t : -1;
                }
                int t = q[ptq & 3];
                uint32_t bar = fbar0 + 8u * s;
                if (t < 0) {  // sentinel: flip full[s] so consumers see q=-1 and exit
                    asm volatile("mbarrier.arrive.shared.b64 _, [%0];" :: "r"(bar) : "memory");
                    break;
                }
                uint32_t dst = smem_base + (uint32_t)(GUARD + s * SLOT_STRIDE) * 4u;
                const float* src = x + (size_t)((t / C_OUT) * C_IN + (t % C_OUT) * NK + pnk) * PLANE;
                asm volatile("mbarrier.arrive.expect_tx.shared.b64 _, [%0], %1;"
                             :: "r"(bar), "r"((uint32_t)PLANE_BYTES) : "memory");
                asm volatile("cp.async.bulk.shared::cta.global.mbarrier::complete_tx::bytes "
                             "[%0], [%1], %2, [%3];"
                             :: "r"(dst), "l"(src), "r"((uint32_t)PLANE_BYTES), "r"(bar) : "memory");
                if (++pnk == NK) { pnk = 0; ptq++; }
            }
        }
        return;
    }

    // ================= compute warps =================
    // Mapping: wp = tid%28 -> w = 2*wp (pair), h0 = tid/28 (0..31), h = h0 + 32k.
    const int wp  = tid % 28;
    const int h0  = tid / 28;
    const int col = 2*wp + EP;            // even -> float2 loads 8B-aligned
    const int rb0 = (h0 + EP) * HIN;
    const int vrow0 = h0 + EP;
    const bool k1 = (h0 < 24);            // k=1 valid only for h0<24
    const int KST = k1 ? KSTEP : 0;       // invalid lanes re-read k=0 (safe, discarded)
    const bool lane0 = ((tid & 31) == 0);

    int p = 0, tq = 0;
    for (;;) {
        int s = p % NSLOT;
        mbar_wait(fbar0 + 8u * s, (p / NSLOT) & 1);   // plane 0 ready; q visible
        const int t = q[tq & 3];
        if (t < 0) break;
        const int co = t % C_OUT, b = t / C_OUT, c0 = co * NK;

        // Double-buffered term tables for this tile.
        float4* tb = tab + (tq & 1) * 44;
        float*  wb = wid + (tq & 1) * 12;
        if (tid < 44) {
            int nk = tid >> 2, g = tid & 3, c = c0 + nk;
            float4 e;
            e.x = __int_as_float(pad_hv[c*8 + g]);
            e.y = w1[g*C_IN + c];
            e.z = __int_as_float(pad_hv[c*8 + 4 + g]);
            e.w = w2[g*C_IN + c];
            tb[tid] = e;
        }
        if (tid >= 64 && tid < 64 + NK) {
            int nk = tid - 64;
            float sw = 0.f;
            #pragma unroll
            for (int g = 0; g < 4; g++)
                if (idx_identit[co*4 + g] - c0 == nk) sw += w3[g*C_OUT + co];
            wb[nk] = sw;
        }
        asm volatile("bar.sync 1, %0;" :: "n"(NCW*32) : "memory");  // tables ready

        unsigned long long acc_h[2] = {0ull, 0ull};   // {w,w+1} x {k0,k1}
        unsigned long long acc_v[2] = {0ull, 0ull};
        unsigned long long acc_i[2] = {0ull, 0ull};

        for (int nk = 0; nk < NK; nk++) {
            s = p % NSLOT;
            if (nk) mbar_wait(fbar0 + 8u * s, (p / NSLOT) & 1);
            const float* base = smem + GUARD + s * SLOT_STRIDE;
            const float* bh = base + rb0;
            const float* bv = base + col;

            #pragma unroll
            for (int g = 0; g < 4; g++) {
                float4 e = tb[nk*4 + g];
                int   sh = __float_as_int(e.x);
                float wh = e.y;
                int   sv = __float_as_int(e.z);
                float wv = e.w;

                // --- horizontal: weight zeroed when either of (w, w+1) is OOB
                //     handled per-half; addresses always safe (guards).
                int iw = col + sh;
                float wt0 = ((unsigned)iw       < (unsigned)HIN) ? wh : 0.0f;
                float wt1 = ((unsigned)(iw + 1) < (unsigned)HIN) ? wh : 0.0f;
                unsigned long long wh2 = pk2(wt0, wt1);
                const float* ph = bh + iw;
                if (sh & 1) {                 // warp-uniform branch (sh broadcast)
                    ffma2(acc_h[0], pk2(ph[0],   ph[1]),       wh2);
                    ffma2(acc_h[1], pk2(ph[KST], ph[KST + 1]), wh2);
                } else {
                    ffma2(acc_h[0], lds64(ph),       wh2);
                    ffma2(acc_h[1], lds64(ph + KST), wh2);
                }

                // --- vertical: OOB rows hit this slot's zero guards (exact 0)
                unsigned long long wv2 = pk2(wv, wv);
                const float* pv = bv + (vrow0 + sv) * HIN;   // even addr -> aligned
                ffma2(acc_v[0], lds64(pv),       wv2);
                ffma2(acc_v[1], lds64(pv + KST), wv2);
            }

            float wi = wb[nk];
            if (wi != 0.0f) {      // warp-uniform branch
                unsigned long long wi2 = pk2(wi, wi);
                const float* pi = bh + col;
                ffma2(acc_i[0], lds64(pi),       wi2);
                ffma2(acc_i[1], lds64(pi + KST), wi2);
            }

            // Warp done with slot s. Acc register deps force all this plane's
            // LDS->FFMA2 chains complete before the arrive issues -> producer
            // can never overwrite data still being read.
            if (lane0) {
                asm volatile("mbarrier.arrive.release.cta.shared::cta.b64 _, [%0];"
                    :: "r"(ebar0 + 8u * s),
                       "l"(acc_h[0]), "l"(acc_h[1]),
                       "l"(acc_v[0]), "l"(acc_v[1]),
                       "l"(acc_i[0]), "l"(acc_i[1])
                    : "memory");
            }
            p++;
        }

        // Write outputs: float2 stores, consecutive lanes -> consecutive pairs.
        float* oh = out;
        float* ov = out + OUT_PLANE;
        float* oi = out + 2*OUT_PLANE;
        const size_t obase = ((size_t)(b * C_OUT + co)) * NPIX + (size_t)h0 * WOUT + 2*wp;
        *(float2*)(oh + obase) = unpk2(acc_h[0]);
        *(float2*)(ov + obase) = unpk2(acc_v[0]);
        *(float2*)(oi + obase) = unpk2(acc_i[0]);
        if (k1) {
            const size_t o1 = obase + (size_t)KROWS * WOUT;
            *(float2*)(oh + o1) = unpk2(acc_h[1]);
            *(float2*)(ov + o1) = unpk2(acc_v[1]);
            *(float2*)(oi + o1) = unpk2(acc_i[1]);
        }
        tq++;
    }
}

extern "C" void kernel_launch(void* const* d_in, const int* in_sizes, int n_in,
                              void* d_out, int out_size)
{
    const float* x           = (const float*)d_in[0];
    const float* w1          = (const float*)d_in[1];
    const float* w2          = (const float*)d_in[2];
    const float* w3          = (const float*)d_in[3];
    const int*   pad_hv      = (const int*)  d_in[4];
    const int*   idx_identit = (const int*)  d_in[5];
    float*       out         = (float*)d_out;

    cudaFuncSetAttribute(addshift_kernel,
                         cudaFuncAttributeMaxDynamicSharedMemorySize, SMEM_BYTES);

    reset_kernel<<<1, 32>>>();
    addshift_kernel<<<148, THREADS, SMEM_BYTES>>>(x, w1, w2, w3, pad_hv,
                                                  idx_identit, out);
}

// round 9
// speedup vs baseline: 1.0523x; 1.0523x over previous
#include <cuda_runtime.h>
#include <cstdint>

// Problem constants (fixed by the reference).
#define C_OUT   96
#define NK      11
#define C_IN    1056
#define GB      8
#define NTILES  (C_OUT*GB)         // 768 tiles, one per (b, c_out)
#define HOUT    56
#define WOUT    56
#define HIN     60
#define EP      2
#define PLANE   3600
#define PLANE_BYTES 14400
#define NPIX    3136
#define NCW     28                 // compute warps
#define THREADS (NCW*32 + 32)      // 928: 28 compute warps + 1 producer warp
#define OUT_PLANE ((size_t)GB*C_OUT*NPIX)
#define KROWS   32                 // h = h0 + 32*k, k in {0,1}
#define KSTEP   (KROWS*HIN)        // 1920 floats

// Plane ring with shared inter-slot zero guards.
// v-row index in [-27, 86] -> offsets [-1618, +5217] from plane start;
// 1620-float guards (shared between adjacent slots) absorb all OOB reads.
#define NSLOT       10
#define GUARD       1620
#define SLOT_STRIDE (PLANE + GUARD)                 // 5220
#define SM_DATA     (NSLOT*SLOT_STRIDE + GUARD)     // 53820 floats
#define OFF_TAB     SM_DATA                          // 2 x 44 float4 (double buffer)
#define OFF_WID     (OFF_TAB + 352)                  // 2 x 12 floats
#define OFF_Q       (OFF_WID + 24)                   // 4 ints (tile queue)
#define OFF_BAR     (OFF_Q + 4)                      // 10 full + 10 empty u64
#define SMEM_FLOATS (OFF_BAR + 40)
#define SMEM_BYTES  (SMEM_FLOATS * 4)                // ~217 KB

__device__ int g_tile_ctr;
__global__ void reset_kernel() { g_tile_ctr = 0; }

__device__ __forceinline__ uint32_t smem_u32(const void* p) {
    uint32_t a;
    asm("{ .reg .u64 t; cvta.to.shared.u64 t, %1; cvt.u32.u64 %0, t; }"
        : "=r"(a) : "l"(p));
    return a;
}
__device__ __forceinline__ void mbar_init(uint32_t mbar, uint32_t cnt) {
    asm volatile("mbarrier.init.shared.b64 [%0], %1;" :: "r"(mbar), "r"(cnt) : "memory");
}
__device__ __forceinline__ void mbar_wait(uint32_t mbar, int parity) {
    asm volatile(
        "{\n\t.reg .pred P;\n"
        "W_%=:\n\t"
        "mbarrier.try_wait.parity.acquire.cta.shared::cta.b64 P, [%0], %1, 0x989680;\n\t"
        "@P bra D_%=;\n\t"
        "bra W_%=;\n"
        "D_%=:\n\t}"
        :: "r"(mbar), "r"(parity) : "memory");
}

// Packed f32x2 helpers (Blackwell: FFMA2 only reachable via PTX fma.rn.f32x2).
__device__ __forceinline__ unsigned long long pk2(float a, float b) {
    unsigned long long r;
    asm("mov.b64 %0, {%1, %2};" : "=l"(r) : "f"(a), "f"(b));
    return r;
}
__device__ __forceinline__ void ffma2(unsigned long long& d,
                                      unsigned long long a, unsigned long long b) {
    asm("fma.rn.f32x2 %0, %1, %2, %0;" : "+l"(d) : "l"(a), "l"(b));
}
__device__ __forceinline__ float2 unpk2(unsigned long long v) {
    float2 r;
    asm("mov.b64 {%0, %1}, %2;" : "=f"(r.x), "=f"(r.y) : "l"(v));
    return r;
}
__device__ __forceinline__ unsigned long long lds64(const float* p) {
    return *reinterpret_cast<const unsigned long long*>(p);   // 8B-aligned by construction
}

__global__ __launch_bounds__(THREADS, 1)
void addshift_kernel(const float* __restrict__ x,
                     const float* __restrict__ w1,
                     const float* __restrict__ w2,
                     const float* __restrict__ w3,
                     const int*   __restrict__ pad_hv,
                     const int*   __restrict__ idx_identit,
                     float* __restrict__ out)
{
    extern __shared__ float smem[];
    float4* tab = (float4*)(smem + OFF_TAB);   // [2][44]
    float*  wid = smem + OFF_WID;              // [2][12]
    int*    q   = (int*)(smem + OFF_Q);

    const int tid = threadIdx.x;
    const uint32_t smem_base = smem_u32(smem);
    const uint32_t fbar0 = smem_base + (uint32_t)OFF_BAR * 4u;        // full[s]
    const uint32_t ebar0 = fbar0 + 8u * NSLOT;                        // empty[s]

    // Zero data region once (guards stay zero; plane bytes overwritten by TMA).
    {
        float4* d = (float4*)smem;
        const float4 z = make_float4(0.f, 0.f, 0.f, 0.f);
        for (int i = tid; i < SM_DATA / 4; i += THREADS) d[i] = z;
    }
    if (tid == 0) {
        for (int s = 0; s < NSLOT; s++) {
            mbar_init(fbar0 + 8u * s, 1);
            mbar_init(ebar0 + 8u * s, NCW);
        }
    }
    __syncthreads();   // the only full-CTA barrier

    // ================= producer warp =================
    if (tid >= NCW * 32) {
        if (tid == NCW * 32) {
            asm volatile("fence.proxy.async.shared::cta;" ::: "memory");
            int pnk = 0, ptq = 0;
            for (int p = 0;; p++) {
                int s = p % NSLOT;
                if (p >= NSLOT)
                    mbar_wait(ebar0 + 8u * s, ((p - NSLOT) / NSLOT) & 1);
                if (pnk == 0) {
                    int t = atomicAdd(&g_tile_ctr, 1);
                    q[ptq & 3] = (t < NTILES) ? t : -1;
                }
                int t = q[ptq & 3];
                uint32_t bar = fbar0 + 8u * s;
                if (t < 0) {  // sentinel: flip full[s] so consumers see q=-1 and exit
                    asm volatile("mbarrier.arrive.shared.b64 _, [%0];" :: "r"(bar) : "memory");
                    break;
                }
                uint32_t dst = smem_base + (uint32_t)(GUARD + s * SLOT_STRIDE) * 4u;
                const float* src = x + (size_t)((t / C_OUT) * C_IN + (t % C_OUT) * NK + pnk) * PLANE;
                asm volatile("mbarrier.arrive.expect_tx.shared.b64 _, [%0], %1;"
                             :: "r"(bar), "r"((uint32_t)PLANE_BYTES) : "memory");
                asm volatile("cp.async.bulk.shared::cta.global.mbarrier::complete_tx::bytes "
                             "[%0], [%1], %2, [%3];"
                             :: "r"(dst), "l"(src), "r"((uint32_t)PLANE_BYTES), "r"(bar) : "memory");
                if (++pnk == NK) { pnk = 0; ptq++; }
            }
        }
        return;
    }

    // ================= compute warps =================
    // Mapping: wp = tid%28 -> w = 2*wp (pair), h0 = tid/28 (0..31), h = h0 + 32k.
    const int wp  = tid % 28;
    const int h0  = tid / 28;
    const int col = 2*wp + EP;            // even -> float2 loads 8B-aligned
    const int rb0 = (h0 + EP) * HIN;
    const int vrow0 = h0 + EP;
    const bool k1 = (h0 < 24);            // k=1 valid only for h0<24
    const int KST = k1 ? KSTEP : 0;       // invalid lanes re-read k=0 (safe, discarded)
    const bool lane0 = ((tid & 31) == 0);

    int p = 0, tq = 0;
    for (;;) {
        int s = p % NSLOT;
        mbar_wait(fbar0 + 8u * s, (p / NSLOT) & 1);   // plane 0 ready; q visible
        const int t = q[tq & 3];
        if (t < 0) break;
        const int co = t % C_OUT, b = t / C_OUT, c0 = co * NK;

        // Double-buffered term tables for this tile.
        float4* tb = tab + (tq & 1) * 44;
        float*  wb = wid + (tq & 1) * 12;
        if (tid < 44) {
            int nk = tid >> 2, g = tid & 3, c = c0 + nk;
            float4 e;
            e.x = __int_as_float(pad_hv[c*8 + g]);
            e.y = w1[g*C_IN + c];
            e.z = __int_as_float(pad_hv[c*8 + 4 + g]);
            e.w = w2[g*C_IN + c];
            tb[tid] = e;
        }
        if (tid >= 64 && tid < 64 + NK) {
            int nk = tid - 64;
            float sw = 0.f;
            #pragma unroll
            for (int g = 0; g < 4; g++)
                if (idx_identit[co*4 + g] - c0 == nk) sw += w3[g*C_OUT + co];
            wb[nk] = sw;
        }
        asm volatile("bar.sync 1, %0;" :: "n"(NCW*32) : "memory");  // tables ready

        unsigned long long acc_h[2] = {0ull, 0ull};   // {w,w+1} x {k0,k1}
        unsigned long long acc_v[2] = {0ull, 0ull};
        unsigned long long acc_i[2] = {0ull, 0ull};

        for (int nk = 0; nk < NK; nk++) {
            s = p % NSLOT;
            if (nk) mbar_wait(fbar0 + 8u * s, (p / NSLOT) & 1);
            const float* base = smem + GUARD + s * SLOT_STRIDE;
            const float* bh = base + rb0;
            const float* bv = base + col;

            #pragma unroll
            for (int g = 0; g < 4; g++) {
                float4 e = tb[nk*4 + g];
                int   sh = __float_as_int(e.x);
                float wh = e.y;
                int   sv = __float_as_int(e.z);
                float wv = e.w;

                // --- horizontal: weight zeroed when either of (w, w+1) is OOB
                //     handled per-half; addresses always safe (guards).
                int iw = col + sh;
                float wt0 = ((unsigned)iw       < (unsigned)HIN) ? wh : 0.0f;
                float wt1 = ((unsigned)(iw + 1) < (unsigned)HIN) ? wh : 0.0f;
                unsigned long long wh2 = pk2(wt0, wt1);
                const float* ph = bh + iw;
                if (sh & 1) {                 // warp-uniform branch (sh broadcast)
                    ffma2(acc_h[0], pk2(ph[0],   ph[1]),       wh2);
                    ffma2(acc_h[1], pk2(ph[KST], ph[KST + 1]), wh2);
                } else {
                    ffma2(acc_h[0], lds64(ph),       wh2);
                    ffma2(acc_h[1], lds64(ph + KST), wh2);
                }

                // --- vertical: OOB rows hit this slot's zero guards (exact 0)
                unsigned long long wv2 = pk2(wv, wv);
                const float* pv = bv + (vrow0 + sv) * HIN;   // even addr -> aligned
                ffma2(acc_v[0], lds64(pv),       wv2);
                ffma2(acc_v[1], lds64(pv + KST), wv2);
            }

            float wi = wb[nk];
            if (wi != 0.0f) {      // warp-uniform branch
                unsigned long long wi2 = pk2(wi, wi);
                const float* pi = bh + col;
                ffma2(acc_i[0], lds64(pi),       wi2);
                ffma2(acc_i[1], lds64(pi + KST), wi2);
            }

            // Warp done with slot s. Acc register deps force all this plane's
            // LDS->FFMA2 chains complete before the arrive issues -> producer
            // can never overwrite data still being read.
            if (lane0) {
                asm volatile("mbarrier.arrive.release.cta.shared::cta.b64 _, [%0];"
                    :: "r"(ebar0 + 8u * s),
                       "l"(acc_h[0]), "l"(acc_h[1]),
                       "l"(acc_v[0]), "l"(acc_v[1]),
                       "l"(acc_i[0]), "l"(acc_i[1])
                    : "memory");
            }
            p++;
        }

        // Write outputs: float2 stores, consecutive lanes -> consecutive pairs.
        float* oh = out;
        float* ov = out + OUT_PLANE;
        float* oi = out + 2*OUT_PLANE;
        const size_t obase = ((size_t)(b * C_OUT + co)) * NPIX + (size_t)h0 * WOUT + 2*wp;
        *(float2*)(oh + obase) = unpk2(acc_h[0]);
        *(float2*)(ov + obase) = unpk2(acc_v[0]);
        *(float2*)(oi + obase) = unpk2(acc_i[0]);
        if (k1) {
            const size_t o1 = obase + (size_t)KROWS * WOUT;
            *(float2*)(oh + o1) = unpk2(acc_h[1]);
            *(float2*)(ov + o1) = unpk2(acc_v[1]);
            *(float2*)(oi + o1) = unpk2(acc_i[1]);
        }
        tq++;
    }
}

extern "C" void kernel_launch(void* const* d_in, const int* in_sizes, int n_in,
                              void* d_out, int out_size)
{
    const float* x           = (const float*)d_in[0];
    const float* w1          = (const float*)d_in[1];
    const float* w2          = (const float*)d_in[2];
    const float* w3          = (const float*)d_in[3];
    const int*   pad_hv      = (const int*)  d_in[4];
    const int*   idx_identit = (const int*)  d_in[5];
    float*       out         = (float*)d_out;

    cudaFuncSetAttribute(addshift_kernel,
                         cudaFuncAttributeMaxDynamicSharedMemorySize, SMEM_BYTES);

    reset_kernel<<<1, 32>>>();
    addshift_kernel<<<148, THREADS, SMEM_BYTES>>>(x, w1, w2, w3, pad_hv,
                                                  idx_identit, out);
}

// round 10
// speedup vs baseline: 1.4697x; 1.3967x over previous
#include <cuda_runtime.h>
#include <cstdint>

// Problem constants (fixed by the reference).
#define C_OUT   96
#define NK      11
#define C_IN    1056
#define GB      8
#define NTILES  (C_OUT*GB)         // 768 tiles, one per (b, c_out)
#define HOUT    56
#define WOUT    56
#define HIN     60
#define EP      2
#define PLANE   3600
#define PLANE_BYTES 14400
#define NPIX    3136
#define NCW     28                 // compute warps: 14 rows x 2 warps/row
#define THREADS (NCW*32 + 32)      // 928: 28 compute warps + 1 producer warp
#define OUT_PLANE ((size_t)GB*C_OUT*NPIX)
#define KROWS   14                 // h = h0 + 14*k, k = 0..3 (14*4 = 56 exact)
#define ROWSTEP (KROWS*HIN)        // 840

// Plane ring with shared inter-slot zero guards.
// v-row index in [-25, 86] -> offsets within [-1618, +5217] of plane start;
// 1620-float guards (shared between adjacent slots) absorb all OOB reads,
// including inactive-lane (w 56..63) overreads.
#define NSLOT       10
#define GUARD       1620
#define SLOT_STRIDE (PLANE + GUARD)                 // 5220
#define SM_DATA     (NSLOT*SLOT_STRIDE + GUARD)     // 53820 floats
#define OFF_TAB     SM_DATA                          // 2 x 44 float4 (double buffer)
#define OFF_WID     (OFF_TAB + 352)                  // 2 x 12 floats
#define OFF_Q       (OFF_WID + 24)                   // 4 ints (tile queue)
#define OFF_BAR     (OFF_Q + 4)                      // 10 full + 10 empty u64
#define SMEM_FLOATS (OFF_BAR + 40)
#define SMEM_BYTES  (SMEM_FLOATS * 4)                // ~217 KB

__device__ int g_tile_ctr;
__global__ void reset_kernel() { g_tile_ctr = 0; }

__device__ __forceinline__ uint32_t smem_u32(const void* p) {
    uint32_t a;
    asm("{ .reg .u64 t; cvta.to.shared.u64 t, %1; cvt.u32.u64 %0, t; }"
        : "=r"(a) : "l"(p));
    return a;
}
__device__ __forceinline__ void mbar_init(uint32_t mbar, uint32_t cnt) {
    asm volatile("mbarrier.init.shared.b64 [%0], %1;" :: "r"(mbar), "r"(cnt) : "memory");
}
__device__ __forceinline__ void mbar_wait(uint32_t mbar, int parity) {
    asm volatile(
        "{\n\t.reg .pred P;\n"
        "W_%=:\n\t"
        "mbarrier.try_wait.parity.acquire.cta.shared::cta.b64 P, [%0], %1, 0x989680;\n\t"
        "@P bra D_%=;\n\t"
        "bra W_%=;\n"
        "D_%=:\n\t}"
        :: "r"(mbar), "r"(parity) : "memory");
}

__global__ __launch_bounds__(THREADS, 1)
void addshift_kernel(const float* __restrict__ x,
                     const float* __restrict__ w1,
                     const float* __restrict__ w2,
                     const float* __restrict__ w3,
                     const int*   __restrict__ pad_hv,
                     const int*   __restrict__ idx_identit,
                     float* __restrict__ out)
{
    extern __shared__ float smem[];
    float4* tab = (float4*)(smem + OFF_TAB);   // [2][44]
    float*  wid = smem + OFF_WID;              // [2][12]
    int*    q   = (int*)(smem + OFF_Q);

    const int tid = threadIdx.x;
    const uint32_t smem_base = smem_u32(smem);
    const uint32_t fbar0 = smem_base + (uint32_t)OFF_BAR * 4u;        // full[s]
    const uint32_t ebar0 = fbar0 + 8u * NSLOT;                        // empty[s]

    // Zero data region once (guards stay zero; plane bytes overwritten by TMA).
    {
        float4* d = (float4*)smem;
        const float4 z = make_float4(0.f, 0.f, 0.f, 0.f);
        for (int i = tid; i < SM_DATA / 4; i += THREADS) d[i] = z;
    }
    if (tid == 0) {
        for (int s = 0; s < NSLOT; s++) {
            mbar_init(fbar0 + 8u * s, 1);
            mbar_init(ebar0 + 8u * s, NCW);
        }
    }
    __syncthreads();   // the only full-CTA barrier

    // ================= producer warp =================
    if (tid >= NCW * 32) {
        if (tid == NCW * 32) {
            asm volatile("fence.proxy.async.shared::cta;" ::: "memory");
            int pnk = 0, ptq = 0;
            for (int p = 0;; p++) {
                int s = p % NSLOT;
                if (p >= NSLOT)
                    mbar_wait(ebar0 + 8u * s, ((p - NSLOT) / NSLOT) & 1);
                if (pnk == 0) {
                    int t = atomicAdd(&g_tile_ctr, 1);
                    q[ptq & 3] = (t < NTILES) ? t : -1;
                }
                int t = q[ptq & 3];
                uint32_t bar = fbar0 + 8u * s;
                if (t < 0) {  // sentinel: flip full[s] so consumers see q=-1 and exit
                    asm volatile("mbarrier.arrive.shared.b64 _, [%0];" :: "r"(bar) : "memory");
                    break;
                }
                uint32_t dst = smem_base + (uint32_t)(GUARD + s * SLOT_STRIDE) * 4u;
                const float* src = x + (size_t)((t / C_OUT) * C_IN + (t % C_OUT) * NK + pnk) * PLANE;
                asm volatile("mbarrier.arrive.expect_tx.shared.b64 _, [%0], %1;"
                             :: "r"(bar), "r"((uint32_t)PLANE_BYTES) : "memory");
                asm volatile("cp.async.bulk.shared::cta.global.mbarrier::complete_tx::bytes "
                             "[%0], [%1], %2, [%3];"
                             :: "r"(dst), "l"(src), "r"((uint32_t)PLANE_BYTES), "r"(bar) : "memory");
                if (++pnk == NK) { pnk = 0; ptq++; }
            }
        }
        return;
    }

    // ================= compute warps =================
    // Row-pure mapping: 64 threads (2 warps) per row chunk; each warp's lanes
    // are consecutive addresses in one row -> conflict-free single-phase LDS.
    const int l   = tid & 63;            // lane-in-row 0..63 (active: <56)
    const int h0  = tid >> 6;            // row chunk 0..13
    const int col = l + EP;              // 2..65 (inactive lanes read guards)
    const int rb0 = (h0 + EP) * HIN;
    const int vrow0 = h0 + EP;
    const bool active = (l < WOUT);
    const bool lane0 = ((tid & 31) == 0);

    int p = 0, tq = 0;
    for (;;) {
        int s = p % NSLOT;
        mbar_wait(fbar0 + 8u * s, (p / NSLOT) & 1);   // plane 0 ready; q visible
        const int t = q[tq & 3];
        if (t < 0) break;
        const int co = t % C_OUT, b = t / C_OUT, c0 = co * NK;

        // Double-buffered term tables for this tile.
        float4* tb = tab + (tq & 1) * 44;
        float*  wb = wid + (tq & 1) * 12;
        if (tid < 44) {
            int nk = tid >> 2, g = tid & 3, c = c0 + nk;
            float4 e;
            e.x = __int_as_float(pad_hv[c*8 + g]);
            e.y = w1[g*C_IN + c];
            e.z = __int_as_float(pad_hv[c*8 + 4 + g]);
            e.w = w2[g*C_IN + c];
            tb[tid] = e;
        }
        if (tid >= 64 && tid < 64 + NK) {
            int nk = tid - 64;
            float sw = 0.f;
            #pragma unroll
            for (int g = 0; g < 4; g++)
                if (idx_identit[co*4 + g] - c0 == nk) sw += w3[g*C_OUT + co];
            wb[nk] = sw;
        }
        asm volatile("bar.sync 1, %0;" :: "n"(NCW*32) : "memory");  // tables ready

        float acc_h[4] = {0.f,0.f,0.f,0.f};
        float acc_v[4] = {0.f,0.f,0.f,0.f};
        float acc_i[4] = {0.f,0.f,0.f,0.f};

        for (int nk = 0; nk < NK; nk++) {
            s = p % NSLOT;
            if (nk) mbar_wait(fbar0 + 8u * s, (p / NSLOT) & 1);
            const float* base = smem + GUARD + s * SLOT_STRIDE;
            const float* bh = base + rb0;
            const float* bv = base + col;

            #pragma unroll
            for (int g = 0; g < 4; g++) {
                float4 e = tb[nk*4 + g];
                int   sh = __float_as_int(e.x);
                float wh = e.y;
                int   sv = __float_as_int(e.z);
                float wv = e.w;

                int iw = col + sh;
                float wt = ((unsigned)iw < (unsigned)HIN) ? wh : 0.0f;
                const float* ph = bh + iw;                 // guards keep address safe
                acc_h[0] = fmaf(ph[0],         wt, acc_h[0]);
                acc_h[1] = fmaf(ph[ROWSTEP],   wt, acc_h[1]);
                acc_h[2] = fmaf(ph[2*ROWSTEP], wt, acc_h[2]);
                acc_h[3] = fmaf(ph[3*ROWSTEP], wt, acc_h[3]);

                const float* pv = bv + (vrow0 + sv) * HIN; // OOB rows hit zero guards
                acc_v[0] = fmaf(pv[0],         wv, acc_v[0]);
                acc_v[1] = fmaf(pv[ROWSTEP],   wv, acc_v[1]);
                acc_v[2] = fmaf(pv[2*ROWSTEP], wv, acc_v[2]);
                acc_v[3] = fmaf(pv[3*ROWSTEP], wv, acc_v[3]);
            }

            float wi = wb[nk];
            if (wi != 0.0f) {      // warp-uniform branch
                const float* pi = bh + col;
                acc_i[0] = fmaf(pi[0],         wi, acc_i[0]);
                acc_i[1] = fmaf(pi[ROWSTEP],   wi, acc_i[1]);
                acc_i[2] = fmaf(pi[2*ROWSTEP], wi, acc_i[2]);
                acc_i[3] = fmaf(pi[3*ROWSTEP], wi, acc_i[3]);
            }

            // Warp done with slot s. Acc register deps force all this plane's
            // LDS->FFMA chains to complete before the arrive issues, so the
            // producer can never overwrite data still being read.
            if (lane0) {
                asm volatile("mbarrier.arrive.release.cta.shared::cta.b64 _, [%0];"
                    :: "r"(ebar0 + 8u * s),
                       "f"(acc_h[0]), "f"(acc_h[1]), "f"(acc_h[2]), "f"(acc_h[3]),
                       "f"(acc_v[0]), "f"(acc_v[1]), "f"(acc_v[2]), "f"(acc_v[3]),
                       "f"(acc_i[0]), "f"(acc_i[1]), "f"(acc_i[2]), "f"(acc_i[3])
                    : "memory");
            }
            p++;
        }

        // Write outputs (coalesced; no tail predicate: 14*4 = 56 rows exact).
        if (active) {
            float* oh = out;
            float* ov = out + OUT_PLANE;
            float* oi = out + 2*OUT_PLANE;
            const size_t obase = ((size_t)(b * C_OUT + co)) * NPIX + (size_t)h0 * WOUT + l;
            #pragma unroll
            for (int k = 0; k < 4; k++) {
                size_t idx = obase + (size_t)(KROWS * k) * WOUT;
                oh[idx] = acc_h[k];
                ov[idx] = acc_v[k];
                oi[idx] = acc_i[k];
            }
        }
        tq++;
    }
}

extern "C" void kernel_launch(void* const* d_in, const int* in_sizes, int n_in,
                              void* d_out, int out_size)
{
    const float* x           = (const float*)d_in[0];
    const float* w1          = (const float*)d_in[1];
    const float* w2          = (const float*)d_in[2];
    const float* w3          = (const float*)d_in[3];
    const int*   pad_hv      = (const int*)  d_in[4];
    const int*   idx_identit = (const int*)  d_in[5];
    float*       out         = (float*)d_out;

    cudaFuncSetAttribute(addshift_kernel,
                         cudaFuncAttributeMaxDynamicSharedMemorySize, SMEM_BYTES);

    reset_kernel<<<1, 32>>>();
    addshift_kernel<<<148, THREADS, SMEM_BYTES>>>(x, w1, w2, w3, pad_hv,
                                                  idx_identit, out);
}

// round 11
// speedup vs baseline: 1.4799x; 1.0069x over previous
#include <cuda_runtime.h>
#include <cstdint>

// Problem constants (fixed by the reference).
#define C_OUT   96
#define NK      11
#define C_IN    1056
#define GB      8
#define NTILES  (C_OUT*GB)         // 768 tiles, one per (b, c_out)
#define HOUT    56
#define WOUT    56
#define HIN     60
#define EP      2
#define PLANE   3600
#define PLANE_BYTES 14400
#define NPIX    3136
#define NCW     28                 // compute warps
#define THREADS (NCW*32 + 32)      // 928: 28 compute warps + 1 producer warp
#define OUT_PLANE ((size_t)GB*C_OUT*NPIX)

// h mapping: 64 threads (2 warps) per row chunk, h = h0h + 14k, k = 0..3
#define KROWS_H 14
#define RSTEP_H (KROWS_H*HIN)      // 840
// v/id mapping: 1 warp per row chunk (28 active lanes x 2 w), h = h0v + 28k, k = 0..1
#define KROWS_V 28
#define RSTEP_V (KROWS_V*HIN)      // 1680

// Plane ring with shared inter-slot zero guards.
// v-row index in [-27, 78] -> offsets within [-1618, +4747] of plane start;
// 1620-float guards (shared between adjacent slots) absorb all OOB reads,
// including inactive-lane overreads in both mappings.
#define NSLOT       10
#define GUARD       1620
#define SLOT_STRIDE (PLANE + GUARD)                 // 5220
#define SM_DATA     (NSLOT*SLOT_STRIDE + GUARD)     // 53820 floats
#define OFF_TAB     SM_DATA                          // 2 x 44 float4 (double buffer)
#define OFF_WID     (OFF_TAB + 352)                  // 2 x 12 floats
#define OFF_Q       (OFF_WID + 24)                   // 4 ints (tile queue)
#define OFF_BAR     (OFF_Q + 4)                      // 10 full + 10 empty u64
#define SMEM_FLOATS (OFF_BAR + 40)
#define SMEM_BYTES  (SMEM_FLOATS * 4)                // ~217 KB

__device__ int g_tile_ctr;
__global__ void reset_kernel() { g_tile_ctr = 0; }

__device__ __forceinline__ uint32_t smem_u32(const void* p) {
    uint32_t a;
    asm("{ .reg .u64 t; cvta.to.shared.u64 t, %1; cvt.u32.u64 %0, t; }"
        : "=r"(a) : "l"(p));
    return a;
}
__device__ __forceinline__ void mbar_init(uint32_t mbar, uint32_t cnt) {
    asm volatile("mbarrier.init.shared.b64 [%0], %1;" :: "r"(mbar), "r"(cnt) : "memory");
}
__device__ __forceinline__ void mbar_wait(uint32_t mbar, int parity) {
    asm volatile(
        "{\n\t.reg .pred P;\n"
        "W_%=:\n\t"
        "mbarrier.try_wait.parity.acquire.cta.shared::cta.b64 P, [%0], %1, 0x989680;\n\t"
        "@P bra D_%=;\n\t"
        "bra W_%=;\n"
        "D_%=:\n\t}"
        :: "r"(mbar), "r"(parity) : "memory");
}

__global__ __launch_bounds__(THREADS, 1)
void addshift_kernel(const float* __restrict__ x,
                     const float* __restrict__ w1,
                     const float* __restrict__ w2,
                     const float* __restrict__ w3,
                     const int*   __restrict__ pad_hv,
                     const int*   __restrict__ idx_identit,
                     float* __restrict__ out)
{
    extern __shared__ float smem[];
    float4* tab = (float4*)(smem + OFF_TAB);   // [2][44]
    float*  wid = smem + OFF_WID;              // [2][12]
    int*    q   = (int*)(smem + OFF_Q);

    const int tid = threadIdx.x;
    const uint32_t smem_base = smem_u32(smem);
    const uint32_t fbar0 = smem_base + (uint32_t)OFF_BAR * 4u;        // full[s]
    const uint32_t ebar0 = fbar0 + 8u * NSLOT;                        // empty[s]

    // Zero data region once (guards stay zero; plane bytes overwritten by TMA).
    {
        float4* d = (float4*)smem;
        const float4 z = make_float4(0.f, 0.f, 0.f, 0.f);
        for (int i = tid; i < SM_DATA / 4; i += THREADS) d[i] = z;
    }
    if (tid == 0) {
        for (int s = 0; s < NSLOT; s++) {
            mbar_init(fbar0 + 8u * s, 1);
            mbar_init(ebar0 + 8u * s, NCW);
        }
    }
    __syncthreads();   // the only full-CTA barrier

    // ================= producer warp =================
    if (tid >= NCW * 32) {
        if (tid == NCW * 32) {
            asm volatile("fence.proxy.async.shared::cta;" ::: "memory");
            int pnk = 0, ptq = 0;
            for (int p = 0;; p++) {
                int s = p % NSLOT;
                if (p >= NSLOT)
                    mbar_wait(ebar0 + 8u * s, ((p - NSLOT) / NSLOT) & 1);
                if (pnk == 0) {
                    int t = atomicAdd(&g_tile_ctr, 1);
                    q[ptq & 3] = (t < NTILES) ? t : -1;
                }
                int t = q[ptq & 3];
                uint32_t bar = fbar0 + 8u * s;
                if (t < 0) {  // sentinel: flip full[s] so consumers see q=-1 and exit
                    asm volatile("mbarrier.arrive.shared.b64 _, [%0];" :: "r"(bar) : "memory");
                    break;
                }
                uint32_t dst = smem_base + (uint32_t)(GUARD + s * SLOT_STRIDE) * 4u;
                const float* src = x + (size_t)((t / C_OUT) * C_IN + (t % C_OUT) * NK + pnk) * PLANE;
                asm volatile("mbarrier.arrive.expect_tx.shared.b64 _, [%0], %1;"
                             :: "r"(bar), "r"((uint32_t)PLANE_BYTES) : "memory");
                asm volatile("cp.async.bulk.shared::cta.global.mbarrier::complete_tx::bytes "
                             "[%0], [%1], %2, [%3];"
                             :: "r"(dst), "l"(src), "r"((uint32_t)PLANE_BYTES), "r"(bar) : "memory");
                if (++pnk == NK) { pnk = 0; ptq++; }
            }
        }
        return;
    }

    // ================= compute warps =================
    // h mapping (scalar, row-pure): 64 threads per row chunk.
    const int lh   = tid & 63;            // 0..63 (active < 56)
    const int h0h  = tid >> 6;            // 0..13
    const int colh = lh + EP;
    const int rb0h = (h0h + EP) * HIN;
    const bool act_h = (lh < WOUT);
    // v/id mapping (2-wide float2, row-pure): 1 warp per row chunk.
    const int l2   = tid & 31;            // 0..31 (active < 28)
    const int h0v  = tid >> 5;            // 0..27
    const int col0 = 2*l2 + EP;           // even -> LDS.64 aligned
    const int vrow0 = h0v + EP;
    const int rb0v = vrow0 * HIN;
    const bool act_v = (l2 < 28);
    const bool lane0 = (l2 == 0);

    int p = 0, tq = 0;
    for (;;) {
        int s = p % NSLOT;
        mbar_wait(fbar0 + 8u * s, (p / NSLOT) & 1);   // plane 0 ready; q visible
        const int t = q[tq & 3];
        if (t < 0) break;
        const int co = t % C_OUT, b = t / C_OUT, c0 = co * NK;

        // Double-buffered term tables for this tile.
        float4* tb = tab + (tq & 1) * 44;
        float*  wb = wid + (tq & 1) * 12;
        if (tid < 44) {
            int nk = tid >> 2, g = tid & 3, c = c0 + nk;
            float4 e;
            e.x = __int_as_float(pad_hv[c*8 + g]);
            e.y = w1[g*C_IN + c];
            e.z = __int_as_float(pad_hv[c*8 + 4 + g]);
            e.w = w2[g*C_IN + c];
            tb[tid] = e;
        }
        if (tid >= 64 && tid < 64 + NK) {
            int nk = tid - 64;
            float sw = 0.f;
            #pragma unroll
            for (int g = 0; g < 4; g++)
                if (idx_identit[co*4 + g] - c0 == nk) sw += w3[g*C_OUT + co];
            wb[nk] = sw;
        }
        asm volatile("bar.sync 1, %0;" :: "n"(NCW*32) : "memory");  // tables ready

        float  acc_h[4] = {0.f,0.f,0.f,0.f};
        float2 acc_v0 = {0.f,0.f}, acc_v1 = {0.f,0.f};
        float2 acc_i0 = {0.f,0.f}, acc_i1 = {0.f,0.f};

        for (int nk = 0; nk < NK; nk++) {
            s = p % NSLOT;
            if (nk) mbar_wait(fbar0 + 8u * s, (p / NSLOT) & 1);
            const float* base = smem + GUARD + s * SLOT_STRIDE;
            const float* bh = base + rb0h;
            const float* bv = base + col0;

            #pragma unroll
            for (int g = 0; g < 4; g++) {
                float4 e = tb[nk*4 + g];
                int   sh = __float_as_int(e.x);
                float wh = e.y;
                int   sv = __float_as_int(e.z);
                float wv = e.w;

                // --- horizontal (scalar mapping): weight zeroed when OOB
                int iw = colh + sh;
                float wt = ((unsigned)iw < (unsigned)HIN) ? wh : 0.0f;
                const float* ph = bh + iw;
                acc_h[0] = fmaf(ph[0],         wt, acc_h[0]);
                acc_h[1] = fmaf(ph[RSTEP_H],   wt, acc_h[1]);
                acc_h[2] = fmaf(ph[2*RSTEP_H], wt, acc_h[2]);
                acc_h[3] = fmaf(ph[3*RSTEP_H], wt, acc_h[3]);

                // --- vertical (float2 mapping): OOB rows hit zero guards
                const float* pv = bv + (vrow0 + sv) * HIN;
                float2 a = *(const float2*)pv;
                float2 c2 = *(const float2*)(pv + RSTEP_V);
                acc_v0.x = fmaf(a.x,  wv, acc_v0.x);
                acc_v0.y = fmaf(a.y,  wv, acc_v0.y);
                acc_v1.x = fmaf(c2.x, wv, acc_v1.x);
                acc_v1.y = fmaf(c2.y, wv, acc_v1.y);
            }

            float wi = wb[nk];
            if (wi != 0.0f) {      // warp-uniform branch
                const float* pi = base + rb0v + col0;
                float2 a = *(const float2*)pi;
                float2 c2 = *(const float2*)(pi + RSTEP_V);
                acc_i0.x = fmaf(a.x,  wi, acc_i0.x);
                acc_i0.y = fmaf(a.y,  wi, acc_i0.y);
                acc_i1.x = fmaf(c2.x, wi, acc_i1.x);
                acc_i1.y = fmaf(c2.y, wi, acc_i1.y);
            }

            // Warp done with slot s. Acc register deps force all this plane's
            // LDS->FFMA chains to complete before the arrive issues, so the
            // producer can never overwrite data still being read.
            if (lane0) {
                asm volatile("mbarrier.arrive.release.cta.shared::cta.b64 _, [%0];"
                    :: "r"(ebar0 + 8u * s),
                       "f"(acc_h[0]), "f"(acc_h[1]), "f"(acc_h[2]), "f"(acc_h[3]),
                       "f"(acc_v0.x), "f"(acc_v0.y), "f"(acc_v1.x), "f"(acc_v1.y),
                       "f"(acc_i0.x), "f"(acc_i0.y), "f"(acc_i1.x), "f"(acc_i1.y)
                    : "memory");
            }
            p++;
        }

        // Write outputs.
        float* oh = out;
        float* ov = out + OUT_PLANE;
        float* oi = out + 2*OUT_PLANE;
        const size_t tbase = ((size_t)(b * C_OUT + co)) * NPIX;
        if (act_h) {
            const size_t ob = tbase + (size_t)h0h * WOUT + lh;
            #pragma unroll
            for (int k = 0; k < 4; k++)
                oh[ob + (size_t)(KROWS_H * k) * WOUT] = acc_h[k];
        }
        if (act_v) {
            const size_t ob = tbase + (size_t)h0v * WOUT + 2*l2;
            *(float2*)(ov + ob) = acc_v0;
            *(float2*)(oi + ob) = acc_i0;
            const size_t ob1 = ob + (size_t)KROWS_V * WOUT;
            *(float2*)(ov + ob1) = acc_v1;
            *(float2*)(oi + ob1) = acc_i1;
        }
        tq++;
    }
}

extern "C" void kernel_launch(void* const* d_in, const int* in_sizes, int n_in,
                              void* d_out, int out_size)
{
    const float* x           = (const float*)d_in[0];
    const float* w1          = (const float*)d_in[1];
    const float* w2          = (const float*)d_in[2];
    const float* w3          = (const float*)d_in[3];
    const int*   pad_hv      = (const int*)  d_in[4];
    const int*   idx_identit = (const int*)  d_in[5];
    float*       out         = (float*)d_out;

    cudaFuncSetAttribute(addshift_kernel,
                         cudaFuncAttributeMaxDynamicSharedMemorySize, SMEM_BYTES);

    reset_kernel<<<1, 32>>>();
    addshift_kernel<<<148, THREADS, SMEM_BYTES>>>(x, w1, w2, w3, pad_hv,
                                                  idx_identit, out);
}

// round 12
// speedup vs baseline: 1.4884x; 1.0058x over previous
#include <cuda_runtime.h>
#include <cstdint>

// Problem constants (fixed by the reference).
#define C_OUT   96
#define NK      11
#define C_IN    1056
#define GB      8
#define NTILES  (C_OUT*GB)         // 768 tiles, one per (b, c_out)
#define HOUT    56
#define WOUT    56
#define HIN     60
#define EP      2
#define PLANE   3600
#define PLANE_BYTES 14400
#define NPIX    3136
#define NCW     28                 // compute warps
#define THREADS (NCW*32 + 32)      // 928: 28 compute warps + 1 producer warp
#define OUT_PLANE ((size_t)GB*C_OUT*NPIX)

// h mapping: 64 threads (2 warps) per row chunk, h = h0h + 14k, k = 0..3
#define KROWS_H 14
#define RSTEP_H (KROWS_H*HIN)      // 840
// v/id mapping: 1 warp per row chunk (28 active lanes x 2 w), h = h0v + 28k, k = 0..1
#define KROWS_V 28
#define RSTEP_V (KROWS_V*HIN)      // 1680

// Plane ring with shared inter-slot zero guards.
// v-row index in [-27, 78] -> offsets within [-1618, +4747] of plane start;
// 1620-float guards (shared between adjacent slots) absorb all OOB reads,
// including inactive-lane overreads in both mappings.
#define NSLOT       10
#define GUARD       1620
#define SLOT_STRIDE (PLANE + GUARD)                 // 5220
#define SM_DATA     (NSLOT*SLOT_STRIDE + GUARD)     // 53820 floats
#define OFF_TAB     SM_DATA                          // 2 x 44 float4 (double buffer)
#define OFF_WID     (OFF_TAB + 352)                  // 2 x 12 floats
#define OFF_Q       (OFF_WID + 24)                   // 4 ints (tile queue)
#define OFF_BAR     (OFF_Q + 4)                      // 10 full + 10 empty u64
#define SMEM_FLOATS (OFF_BAR + 40)
#define SMEM_BYTES  (SMEM_FLOATS * 4)                // ~217 KB

__device__ int g_tile_ctr;
__global__ void reset_kernel() { g_tile_ctr = 0; }

__device__ __forceinline__ uint32_t smem_u32(const void* p) {
    uint32_t a;
    asm("{ .reg .u64 t; cvta.to.shared.u64 t, %1; cvt.u32.u64 %0, t; }"
        : "=r"(a) : "l"(p));
    return a;
}
__device__ __forceinline__ void mbar_init(uint32_t mbar, uint32_t cnt) {
    asm volatile("mbarrier.init.shared.b64 [%0], %1;" :: "r"(mbar), "r"(cnt) : "memory");
}
__device__ __forceinline__ void mbar_wait(uint32_t mbar, int parity) {
    asm volatile(
        "{\n\t.reg .pred P;\n"
        "W_%=:\n\t"
        "mbarrier.try_wait.parity.acquire.cta.shared::cta.b64 P, [%0], %1, 0x989680;\n\t"
        "@P bra D_%=;\n\t"
        "bra W_%=;\n"
        "D_%=:\n\t}"
        :: "r"(mbar), "r"(parity) : "memory");
}

__global__ __launch_bounds__(THREADS, 1)
void addshift_kernel(const float* __restrict__ x,
                     const float* __restrict__ w1,
                     const float* __restrict__ w2,
                     const float* __restrict__ w3,
                     const int*   __restrict__ pad_hv,
                     const int*   __restrict__ idx_identit,
                     float* __restrict__ out)
{
    extern __shared__ float smem[];
    float4* tab = (float4*)(smem + OFF_TAB);   // [2][44]
    float*  wid = smem + OFF_WID;              // [2][12]
    int*    q   = (int*)(smem + OFF_Q);

    const int tid = threadIdx.x;
    const uint32_t smem_base = smem_u32(smem);
    const uint32_t fbar0 = smem_base + (uint32_t)OFF_BAR * 4u;        // full[s]
    const uint32_t ebar0 = fbar0 + 8u * NSLOT;                        // empty[s]

    // Zero data region once (guards stay zero; plane bytes overwritten by TMA).
    {
        float4* d = (float4*)smem;
        const float4 z = make_float4(0.f, 0.f, 0.f, 0.f);
        for (int i = tid; i < SM_DATA / 4; i += THREADS) d[i] = z;
    }
    if (tid == 0) {
        for (int s = 0; s < NSLOT; s++) {
            mbar_init(fbar0 + 8u * s, 1);
            mbar_init(ebar0 + 8u * s, NCW);
        }
    }
    __syncthreads();   // the only full-CTA barrier

    // ================= producer warp =================
    if (tid >= NCW * 32) {
        if (tid == NCW * 32) {
            asm volatile("fence.proxy.async.shared::cta;" ::: "memory");
            int pnk = 0, ptq = 0;
            for (int p = 0;; p++) {
                int s = p % NSLOT;
                if (p >= NSLOT)
                    mbar_wait(ebar0 + 8u * s, ((p - NSLOT) / NSLOT) & 1);
                if (pnk == 0) {
                    int t = atomicAdd(&g_tile_ctr, 1);
                    q[ptq & 3] = (t < NTILES) ? t : -1;
                }
                int t = q[ptq & 3];
                uint32_t bar = fbar0 + 8u * s;
                if (t < 0) {  // sentinel: flip full[s] so consumers see q=-1 and exit
                    asm volatile("mbarrier.arrive.shared.b64 _, [%0];" :: "r"(bar) : "memory");
                    break;
                }
                uint32_t dst = smem_base + (uint32_t)(GUARD + s * SLOT_STRIDE) * 4u;
                const float* src = x + (size_t)((t / C_OUT) * C_IN + (t % C_OUT) * NK + pnk) * PLANE;
                asm volatile("mbarrier.arrive.expect_tx.shared.b64 _, [%0], %1;"
                             :: "r"(bar), "r"((uint32_t)PLANE_BYTES) : "memory");
                asm volatile("cp.async.bulk.shared::cta.global.mbarrier::complete_tx::bytes "
                             "[%0], [%1], %2, [%3];"
                             :: "r"(dst), "l"(src), "r"((uint32_t)PLANE_BYTES), "r"(bar) : "memory");
                if (++pnk == NK) { pnk = 0; ptq++; }
            }
        }
        return;
    }

    // ================= compute warps =================
    // h mapping (scalar, row-pure): 64 threads per row chunk.
    const int lh   = tid & 63;            // 0..63 (active < 56)
    const int h0h  = tid >> 6;            // 0..13
    const int colh = lh + EP;
    const int rb0h = (h0h + EP) * HIN;
    const bool act_h = (lh < WOUT);
    // v/id mapping (2-wide float2, row-pure): 1 warp per row chunk.
    const int l2   = tid & 31;            // 0..31 (active < 28)
    const int h0v  = tid >> 5;            // 0..27
    const int col0 = 2*l2 + EP;           // even -> LDS.64 aligned
    const int vrow0 = h0v + EP;
    const int rb0v = vrow0 * HIN;
    const bool act_v = (l2 < 28);
    const bool lane0 = (l2 == 0);

    int p = 0, tq = 0;
    for (;;) {
        int s = p % NSLOT;
        mbar_wait(fbar0 + 8u * s, (p / NSLOT) & 1);   // plane 0 ready; q visible
        const int t = q[tq & 3];
        if (t < 0) break;
        const int co = t % C_OUT, b = t / C_OUT, c0 = co * NK;

        // Double-buffered term tables for this tile.
        float4* tb = tab + (tq & 1) * 44;
        float*  wb = wid + (tq & 1) * 12;
        if (tid < 44) {
            int nk = tid >> 2, g = tid & 3, c = c0 + nk;
            float4 e;
            e.x = __int_as_float(pad_hv[c*8 + g]);
            e.y = w1[g*C_IN + c];
            e.z = __int_as_float(pad_hv[c*8 + 4 + g]);
            e.w = w2[g*C_IN + c];
            tb[tid] = e;
        }
        if (tid >= 64 && tid < 64 + NK) {
            int nk = tid - 64;
            float sw = 0.f;
            #pragma unroll
            for (int g = 0; g < 4; g++)
                if (idx_identit[co*4 + g] - c0 == nk) sw += w3[g*C_OUT + co];
            wb[nk] = sw;
        }
        asm volatile("bar.sync 1, %0;" :: "n"(NCW*32) : "memory");  // tables ready

        float  acc_h[4] = {0.f,0.f,0.f,0.f};
        float2 acc_v0 = {0.f,0.f}, acc_v1 = {0.f,0.f};
        float2 acc_i0 = {0.f,0.f}, acc_i1 = {0.f,0.f};

        for (int nk = 0; nk < NK; nk++) {
            s = p % NSLOT;
            if (nk) mbar_wait(fbar0 + 8u * s, (p / NSLOT) & 1);
            const float* base = smem + GUARD + s * SLOT_STRIDE;
            const float* bh = base + rb0h;
            const float* bv = base + col0;

            #pragma unroll
            for (int g = 0; g < 4; g++) {
                float4 e = tb[nk*4 + g];
                int   sh = __float_as_int(e.x);
                float wh = e.y;
                int   sv = __float_as_int(e.z);
                float wv = e.w;

                // --- horizontal (scalar mapping): weight zeroed when OOB
                int iw = colh + sh;
                float wt = ((unsigned)iw < (unsigned)HIN) ? wh : 0.0f;
                const float* ph = bh + iw;
                acc_h[0] = fmaf(ph[0],         wt, acc_h[0]);
                acc_h[1] = fmaf(ph[RSTEP_H],   wt, acc_h[1]);
                acc_h[2] = fmaf(ph[2*RSTEP_H], wt, acc_h[2]);
                acc_h[3] = fmaf(ph[3*RSTEP_H], wt, acc_h[3]);

                // --- vertical (float2 mapping): OOB rows hit zero guards
                const float* pv = bv + (vrow0 + sv) * HIN;
                float2 a = *(const float2*)pv;
                float2 c2 = *(const float2*)(pv + RSTEP_V);
                acc_v0.x = fmaf(a.x,  wv, acc_v0.x);
                acc_v0.y = fmaf(a.y,  wv, acc_v0.y);
                acc_v1.x = fmaf(c2.x, wv, acc_v1.x);
                acc_v1.y = fmaf(c2.y, wv, acc_v1.y);
            }

            float wi = wb[nk];
            if (wi != 0.0f) {      // warp-uniform branch
                const float* pi = base + rb0v + col0;
                float2 a = *(const float2*)pi;
                float2 c2 = *(const float2*)(pi + RSTEP_V);
                acc_i0.x = fmaf(a.x,  wi, acc_i0.x);
                acc_i0.y = fmaf(a.y,  wi, acc_i0.y);
                acc_i1.x = fmaf(c2.x, wi, acc_i1.x);
                acc_i1.y = fmaf(c2.y, wi, acc_i1.y);
            }

            // Warp done with slot s. Acc register deps force all this plane's
            // LDS->FFMA chains to complete before the arrive issues, so the
            // producer can never overwrite data still being read.
            if (lane0) {
                asm volatile("mbarrier.arrive.release.cta.shared::cta.b64 _, [%0];"
                    :: "r"(ebar0 + 8u * s),
                       "f"(acc_h[0]), "f"(acc_h[1]), "f"(acc_h[2]), "f"(acc_h[3]),
                       "f"(acc_v0.x), "f"(acc_v0.y), "f"(acc_v1.x), "f"(acc_v1.y),
                       "f"(acc_i0.x), "f"(acc_i0.y), "f"(acc_i1.x), "f"(acc_i1.y)
                    : "memory");
            }
            p++;
        }

        // Write outputs.
        float* oh = out;
        float* ov = out + OUT_PLANE;
        float* oi = out + 2*OUT_PLANE;
        const size_t tbase = ((size_t)(b * C_OUT + co)) * NPIX;
        if (act_h) {
            const size_t ob = tbase + (size_t)h0h * WOUT + lh;
            #pragma unroll
            for (int k = 0; k < 4; k++)
                oh[ob + (size_t)(KROWS_H * k) * WOUT] = acc_h[k];
        }
        if (act_v) {
            const size_t ob = tbase + (size_t)h0v * WOUT + 2*l2;
            *(float2*)(ov + ob) = acc_v0;
            *(float2*)(oi + ob) = acc_i0;
            const size_t ob1 = ob + (size_t)KROWS_V * WOUT;
            *(float2*)(ov + ob1) = acc_v1;
            *(float2*)(oi + ob1) = acc_i1;
        }
        tq++;
    }
}

extern "C" void kernel_launch(void* const* d_in, const int* in_sizes, int n_in,
                              void* d_out, int out_size)
{
    const float* x           = (const float*)d_in[0];
    const float* w1          = (const float*)d_in[1];
    const float* w2          = (const float*)d_in[2];
    const float* w3          = (const float*)d_in[3];
    const int*   pad_hv      = (const int*)  d_in[4];
    const int*   idx_identit = (const int*)  d_in[5];
    float*       out         = (float*)d_out;

    cudaFuncSetAttribute(addshift_kernel,
                         cudaFuncAttributeMaxDynamicSharedMemorySize, SMEM_BYTES);

    reset_kernel<<<1, 32>>>();
    addshift_kernel<<<148, THREADS, SMEM_BYTES>>>(x, w1, w2, w3, pad_hv,
                                                  idx_identit, out);
}